// round 12
// baseline (speedup 1.0000x reference)
#include <cuda_runtime.h>

// out = x^2 * 0.1 over N fp32. HBM-bound streaming kernel.
// Persistent single-wave grid (148 SMs x 8 CTAs x 256 thr), grid-stride loop,
// MLP_p1 pinned to 1 (#pragma unroll 1) to hold cross-CTA L1tex-queue spread
// at its 1.10 floor. R1/R8/R9 evidence: batched loads and exact-fit grids
// both regress vs capped grid-stride; this removes R1's wave-2 and its
// compiler-chosen unroll.

__global__ void __launch_bounds__(256) poly_kernel_pers(const float4* __restrict__ x,
                                                        float4* __restrict__ out,
                                                        int n4) {
    const int stride = gridDim.x * blockDim.x;
#pragma unroll 1
    for (int i = blockIdx.x * blockDim.x + threadIdx.x; i < n4; i += stride) {
        float4 v = x[i];
        float4 r;
        r.x = v.x * v.x * 0.1f;
        r.y = v.y * v.y * 0.1f;
        r.z = v.z * v.z * 0.1f;
        r.w = v.w * v.w * 0.1f;
        out[i] = r;
    }
}

// Scalar tail for n % 4 != 0 (not hit for 64*1024*1024, but safe).
__global__ void poly_kernel_tail(const float* __restrict__ x,
                                 float* __restrict__ out,
                                 int start, int n) {
    int i = start + blockIdx.x * blockDim.x + threadIdx.x;
    if (i < n) {
        float v = x[i];
        out[i] = v * v * 0.1f;
    }
}

extern "C" void kernel_launch(void* const* d_in, const int* in_sizes, int n_in,
                              void* d_out, int out_size) {
    const float* x = (const float*)d_in[0];
    float* out = (float*)d_out;
    int n = in_sizes[0];

    int n4 = n / 4;
    if (n4 > 0) {
        // One exact wave: 148 SMs x (2048 threads / 256) = 1184 CTAs.
        int blocks = 148 * 8;
        int needed = (n4 + 255) / 256;
        if (blocks > needed) blocks = needed;
        poly_kernel_pers<<<blocks, 256>>>((const float4*)x, (float4*)out, n4);
    }

    int rem = n - n4 * 4;
    if (rem > 0) {
        poly_kernel_tail<<<1, 256>>>(x, out, n4 * 4, n);
    }
}

// round 15
// speedup vs baseline: 1.0565x; 1.0565x over previous
#include <cuda_runtime.h>

// out = x^2 * 0.1 over N fp32. HBM-bound streaming kernel.
// Empirical optimum across R1/R8/R9/R12 sweeps: grid-stride, 2368 CTAs x 256,
// explicit pairwise unroll (MLP_p1=2 -> oe*MLP_p1 = 16 = spread-model knee;
// unroll 1 and unroll 4 both measured slower, flat/persistent grids slower).

__global__ void __launch_bounds__(256) poly_kernel_u2(const float4* __restrict__ x,
                                                      float4* __restrict__ out,
                                                      int n4) {
    const int stride = gridDim.x * blockDim.x;
    int i = blockIdx.x * blockDim.x + threadIdx.x;

    // Pairwise unrolled main loop: exactly 2 independent loads in flight.
    for (; i + stride < n4; i += 2 * stride) {
        float4 v0 = x[i];
        float4 v1 = x[i + stride];
        float4 r0, r1;
        r0.x = v0.x * v0.x * 0.1f; r0.y = v0.y * v0.y * 0.1f;
        r0.z = v0.z * v0.z * 0.1f; r0.w = v0.w * v0.w * 0.1f;
        r1.x = v1.x * v1.x * 0.1f; r1.y = v1.y * v1.y * 0.1f;
        r1.z = v1.z * v1.z * 0.1f; r1.w = v1.w * v1.w * 0.1f;
        out[i]          = r0;
        out[i + stride] = r1;
    }
    if (i < n4) {
        float4 v = x[i];
        float4 r;
        r.x = v.x * v.x * 0.1f;
        r.y = v.y * v.y * 0.1f;
        r.z = v.z * v.z * 0.1f;
        r.w = v.w * v.w * 0.1f;
        out[i] = r;
    }
}

// Scalar tail for n % 4 != 0 (not hit for 64*1024*1024, but safe).
__global__ void poly_kernel_tail(const float* __restrict__ x,
                                 float* __restrict__ out,
                                 int start, int n) {
    int i = start + blockIdx.x * blockDim.x + threadIdx.x;
    if (i < n) {
        float v = x[i];
        out[i] = v * v * 0.1f;
    }
}

extern "C" void kernel_launch(void* const* d_in, const int* in_sizes, int n_in,
                              void* d_out, int out_size) {
    const float* x = (const float*)d_in[0];
    float* out = (float*)d_out;
    int n = in_sizes[0];

    int n4 = n / 4;
    if (n4 > 0) {
        const int threads = 256;
        int blocks = (n4 + threads - 1) / threads;
        const int max_blocks = 2368;  // R1's measured-best cap (16 CTAs/SM queued)
        if (blocks > max_blocks) blocks = max_blocks;
        poly_kernel_u2<<<blocks, threads>>>((const float4*)x, (float4*)out, n4);
    }

    int rem = n - n4 * 4;
    if (rem > 0) {
        poly_kernel_tail<<<1, 256>>>(x, out, n4 * 4, n);
    }
}